// round 3
// baseline (speedup 1.0000x reference)
#include <cuda_runtime.h>
#include <math.h>

#define CC 256
#define HH 4
#define NMAX 500000
#define PMAX 50000
#define TP 32

typedef unsigned long long ull;

// ---------------- device scratch ----------------
__device__ float    g_Q[CC];
__device__ float    g_qw[HH * CC];
__device__ float    g_qc[HH];
__device__ float    g_scoreE[(size_t)NMAX * HH];
__device__ unsigned g_smax[PMAX * HH];
__device__ float    g_denom[PMAX * HH];
__device__ int      g_count[PMAX];
__device__ int      g_offsets[PMAX + 1];
__device__ int      g_fill[PMAX];
__device__ int      g_order[NMAX];
__device__ float    g_xbar[(size_t)PMAX * HH * CC];

// ---------------- helpers ----------------
__device__ __forceinline__ unsigned encf(float f) {
    unsigned u = __float_as_uint(f);
    return (u & 0x80000000u) ? ~u : (u | 0x80000000u);
}
__device__ __forceinline__ float decf(unsigned u) {
    return (u & 0x80000000u) ? __uint_as_float(u ^ 0x80000000u) : __uint_as_float(~u);
}
__device__ __forceinline__ float hadd2(ull v) {
    float x, y;
    asm("mov.b64 {%0,%1}, %2;" : "=f"(x), "=f"(y) : "l"(v));
    return x + y;
}
__device__ __forceinline__ void fma2(ull& d, ull a, ull b) {
    asm("fma.rn.f32x2 %0, %1, %2, %0;" : "+l"(d) : "l"(a), "l"(b));
}

// ---------------- kernels ----------------
__global__ void k_init(int P) {
    int i = blockIdx.x * blockDim.x + threadIdx.x;
    int st = gridDim.x * blockDim.x;
    for (int j = i; j < P * HH; j += st) { g_smax[j] = 0u; g_denom[j] = 0.f; }
    for (int j = i; j < P; j += st)      { g_count[j] = 0;  g_fill[j] = 0; }
}

__global__ void k_q(const float* __restrict__ S, const float* __restrict__ Wq,
                    const float* __restrict__ bq) {
    __shared__ float sS[CC];
    int c = threadIdx.x;
    sS[c] = S[c];
    __syncthreads();
    const float4* wr = (const float4*)(Wq + (size_t)c * CC);
    float acc = 0.f;
    #pragma unroll 8
    for (int j = 0; j < CC / 4; j++) {
        float4 w = wr[j];
        acc += sS[4*j] * w.x + sS[4*j+1] * w.y + sS[4*j+2] * w.z + sS[4*j+3] * w.w;
    }
    g_Q[c] = acc + bq[c];
}

__global__ void k_qw(const float* __restrict__ Wk, const float* __restrict__ bk) {
    int h = blockIdx.x;
    int j = threadIdx.x;
    __shared__ float sQ[64];
    if (j < 64) sQ[j] = g_Q[h * 64 + j];
    __syncthreads();
    float acc = 0.f;
    #pragma unroll 8
    for (int cc = 0; cc < 64; cc++)
        acc += sQ[cc] * Wk[(size_t)(h * 64 + cc) * CC + j];
    g_qw[h * CC + j] = acc * 0.0625f;
    if (j == 0) {
        float q = 0.f;
        for (int cc = 0; cc < 64; cc++) q += sQ[cc] * bk[h * 64 + cc];
        g_qc[h] = q * 0.0625f;
    }
}

// warp handles 4 consecutive checkins; qw held in registers
__global__ void k_scores(const float* __restrict__ x, const int* __restrict__ poi, int N) {
    int lane = threadIdx.x & 31;
    int gw = (blockIdx.x * blockDim.x + threadIdx.x) >> 5;
    int n0 = gw * 4;
    if (n0 >= N) return;
    float4 q0[HH], q1[HH];
    #pragma unroll
    for (int h = 0; h < HH; h++) {
        q0[h] = *(const float4*)&g_qw[h * CC + lane * 4];
        q1[h] = *(const float4*)&g_qw[h * CC + 128 + lane * 4];
    }
    float qc0 = g_qc[0], qc1 = g_qc[1], qc2 = g_qc[2], qc3 = g_qc[3];
    #pragma unroll
    for (int j = 0; j < 4; j++) {
        int n = n0 + j;
        if (n >= N) break;
        const float4* xr = (const float4*)(x + (size_t)n * CC);
        float4 x0 = xr[lane];
        float4 x1 = xr[32 + lane];
        float acc[HH];
        #pragma unroll
        for (int h = 0; h < HH; h++) {
            acc[h] = x0.x * q0[h].x + x0.y * q0[h].y + x0.z * q0[h].z + x0.w * q0[h].w
                   + x1.x * q1[h].x + x1.y * q1[h].y + x1.z * q1[h].z + x1.w * q1[h].w;
        }
        #pragma unroll
        for (int off = 16; off > 0; off >>= 1) {
            #pragma unroll
            for (int h = 0; h < HH; h++)
                acc[h] += __shfl_xor_sync(0xffffffffu, acc[h], off);
        }
        if (lane == 0) {
            int p = poi[n];
            float a0 = acc[0] + qc0, a1 = acc[1] + qc1;
            float a2 = acc[2] + qc2, a3 = acc[3] + qc3;
            atomicMax(&g_smax[p * 4 + 0], encf(a0));
            atomicMax(&g_smax[p * 4 + 1], encf(a1));
            atomicMax(&g_smax[p * 4 + 2], encf(a2));
            atomicMax(&g_smax[p * 4 + 3], encf(a3));
            *(float4*)&g_scoreE[(size_t)n * 4] = make_float4(a0, a1, a2, a3);
            atomicAdd(&g_count[p], 1);
        }
    }
}

__global__ void k_scan(int P) {
    __shared__ int s[1024];
    int t = threadIdx.x;
    int chunk = (P + 1023) / 1024;
    int beg = t * chunk, end = min(beg + chunk, P);
    int sum = 0;
    for (int i = beg; i < end; i++) sum += g_count[i];
    s[t] = sum;
    __syncthreads();
    for (int off = 1; off < 1024; off <<= 1) {
        int v = (t >= off) ? s[t - off] : 0;
        __syncthreads();
        s[t] += v;
        __syncthreads();
    }
    int run = s[t] - sum;
    for (int i = beg; i < end; i++) { g_offsets[i] = run; run += g_count[i]; }
    if (t == 1023) g_offsets[P] = s[1023];
}

// merged: e = exp(score - smax); denom += e; CSR scatter
__global__ void k_exp_scatter(const int* __restrict__ poi, int N) {
    int n = blockIdx.x * blockDim.x + threadIdx.x;
    if (n >= N) return;
    float4 s = *(const float4*)&g_scoreE[(size_t)n * 4];
    int p = poi[n];
    float e0 = expf(s.x - decf(g_smax[p * 4 + 0]));
    float e1 = expf(s.y - decf(g_smax[p * 4 + 1]));
    float e2 = expf(s.z - decf(g_smax[p * 4 + 2]));
    float e3 = expf(s.w - decf(g_smax[p * 4 + 3]));
    *(float4*)&g_scoreE[(size_t)n * 4] = make_float4(e0, e1, e2, e3);
    atomicAdd(&g_denom[p * 4 + 0], e0);
    atomicAdd(&g_denom[p * 4 + 1], e1);
    atomicAdd(&g_denom[p * 4 + 2], e2);
    atomicAdd(&g_denom[p * 4 + 3], e3);
    int pos = g_offsets[p] + atomicAdd(&g_fill[p], 1);
    g_order[pos] = n;
}

// xbar[p,h,:] = sum_{n in p} alpha[n,h] * x[n,:]   (warp per POI)
__global__ void k_gather(const float* __restrict__ x, int P) {
    int lane = threadIdx.x & 31;
    int p = (blockIdx.x * blockDim.x + threadIdx.x) >> 5;
    if (p >= P) return;
    int beg = g_offsets[p], end = g_offsets[p + 1];
    float rinv[HH];
    #pragma unroll
    for (int h = 0; h < HH; h++) rinv[h] = 1.0f / (g_denom[p * 4 + h] + 1e-16f);
    float a0[HH][4], a1[HH][4];
    #pragma unroll
    for (int h = 0; h < HH; h++)
        #pragma unroll
        for (int k = 0; k < 4; k++) { a0[h][k] = 0.f; a1[h][k] = 0.f; }
    int n = (beg < end) ? g_order[beg] : 0;
    for (int i = beg; i < end; i++) {
        int nn = (i + 1 < end) ? g_order[i + 1] : 0;      // prefetch index
        float4 e = *(const float4*)&g_scoreE[(size_t)n * 4];
        const float4* xr = (const float4*)(x + (size_t)n * CC);
        float4 v0 = xr[lane];
        float4 v1 = xr[32 + lane];
        float al[HH] = { e.x * rinv[0], e.y * rinv[1], e.z * rinv[2], e.w * rinv[3] };
        #pragma unroll
        for (int h = 0; h < HH; h++) {
            a0[h][0] += al[h] * v0.x; a0[h][1] += al[h] * v0.y;
            a0[h][2] += al[h] * v0.z; a0[h][3] += al[h] * v0.w;
            a1[h][0] += al[h] * v1.x; a1[h][1] += al[h] * v1.y;
            a1[h][2] += al[h] * v1.z; a1[h][3] += al[h] * v1.w;
        }
        n = nn;
    }
    #pragma unroll
    for (int h = 0; h < HH; h++) {
        float* dst = &g_xbar[((size_t)p * HH + h) * CC];
        *(float4*)&dst[lane * 4]       = make_float4(a0[h][0], a0[h][1], a0[h][2], a0[h][3]);
        *(float4*)&dst[128 + lane * 4] = make_float4(a1[h][0], a1[h][1], a1[h][2], a1[h][3]);
    }
}

// Fused register-tiled GEMMs:
//   O = Q + xbar @ Wv[c][k] + bv*m ; out = prelu(O + relu(O @ Wo[c][k] + bo))
// 256 threads: tcol(0..63) -> 4 consecutive cols within one head; tpp(0..3) -> 8 rows.
__global__ void __launch_bounds__(256) k_fused(
    const float* __restrict__ Wv, const float* __restrict__ Wo,
    const float* __restrict__ bv, const float* __restrict__ bo,
    const float* __restrict__ prelu, float* __restrict__ out, int P)
{
    __shared__ float sO[TP * CC];          // 32 KB
    int t = threadIdx.x;
    int tcol = t & 63, tpp = t >> 6;
    int head = tcol >> 4;
    int c0 = head * 64 + (tcol & 15) * 4;
    int p0 = blockIdx.x * TP;
    int rbase = tpp * 8;

    const longlong2* xr[8];
    #pragma unroll
    for (int pp = 0; pp < 8; pp++) {
        int p = p0 + rbase + pp; if (p > P - 1) p = P - 1;
        xr[pp] = (const longlong2*)(g_xbar + ((size_t)p * HH + head) * CC);
    }
    const longlong2* wv[4];
    #pragma unroll
    for (int u = 0; u < 4; u++)
        wv[u] = (const longlong2*)(Wv + (size_t)(c0 + u) * CC);

    ull acc[8][4];
    #pragma unroll
    for (int pp = 0; pp < 8; pp++)
        #pragma unroll
        for (int u = 0; u < 4; u++) acc[pp][u] = 0ull;

    // ---- Phase A ----
    for (int kc = 0; kc < CC / 8; kc++) {
        ull w2[4][4];
        #pragma unroll
        for (int u = 0; u < 4; u++) {
            longlong2 a = wv[u][2 * kc], b = wv[u][2 * kc + 1];
            w2[u][0] = (ull)a.x; w2[u][1] = (ull)a.y;
            w2[u][2] = (ull)b.x; w2[u][3] = (ull)b.y;
        }
        #pragma unroll
        for (int pp = 0; pp < 8; pp++) {
            longlong2 a = xr[pp][2 * kc], b = xr[pp][2 * kc + 1];
            #pragma unroll
            for (int u = 0; u < 4; u++) {
                fma2(acc[pp][u], (ull)a.x, w2[u][0]);
                fma2(acc[pp][u], (ull)a.y, w2[u][1]);
                fma2(acc[pp][u], (ull)b.x, w2[u][2]);
                fma2(acc[pp][u], (ull)b.y, w2[u][3]);
            }
        }
    }
    {
        float qv[4], bvv[4];
        #pragma unroll
        for (int u = 0; u < 4; u++) { qv[u] = g_Q[c0 + u]; bvv[u] = bv[c0 + u]; }
        #pragma unroll
        for (int pp = 0; pp < 8; pp++) {
            int p = p0 + rbase + pp; if (p > P - 1) p = P - 1;
            float d = g_denom[p * 4 + head];
            float m = d / (d + 1e-16f);
            float4 o;
            o.x = hadd2(acc[pp][0]) + qv[0] + bvv[0] * m;
            o.y = hadd2(acc[pp][1]) + qv[1] + bvv[1] * m;
            o.z = hadd2(acc[pp][2]) + qv[2] + bvv[2] * m;
            o.w = hadd2(acc[pp][3]) + qv[3] + bvv[3] * m;
            *(float4*)&sO[(rbase + pp) * CC + c0] = o;
            acc[pp][0] = acc[pp][1] = acc[pp][2] = acc[pp][3] = 0ull;
        }
    }
    __syncthreads();

    // ---- Phase B ----
    const longlong2* wo[4];
    #pragma unroll
    for (int u = 0; u < 4; u++)
        wo[u] = (const longlong2*)(Wo + (size_t)(c0 + u) * CC);

    for (int kc = 0; kc < CC / 8; kc++) {
        ull w2[4][4];
        #pragma unroll
        for (int u = 0; u < 4; u++) {
            longlong2 a = wo[u][2 * kc], b = wo[u][2 * kc + 1];
            w2[u][0] = (ull)a.x; w2[u][1] = (ull)a.y;
            w2[u][2] = (ull)b.x; w2[u][3] = (ull)b.y;
        }
        #pragma unroll
        for (int pp = 0; pp < 8; pp++) {
            const longlong2* sr = (const longlong2*)&sO[(rbase + pp) * CC + kc * 8];
            longlong2 a = sr[0], b = sr[1];
            #pragma unroll
            for (int u = 0; u < 4; u++) {
                fma2(acc[pp][u], (ull)a.x, w2[u][0]);
                fma2(acc[pp][u], (ull)a.y, w2[u][1]);
                fma2(acc[pp][u], (ull)b.x, w2[u][2]);
                fma2(acc[pp][u], (ull)b.y, w2[u][3]);
            }
        }
    }
    {
        float bov[4];
        #pragma unroll
        for (int u = 0; u < 4; u++) bov[u] = bo[c0 + u];
        float pa = prelu[0];
        #pragma unroll
        for (int pp = 0; pp < 8; pp++) {
            int p = p0 + rbase + pp;
            if (p < P) {
                float4 o = *(const float4*)&sO[(rbase + pp) * CC + c0];
                float4 r;
                float t0 = fmaxf(hadd2(acc[pp][0]) + bov[0], 0.f);
                float t1 = fmaxf(hadd2(acc[pp][1]) + bov[1], 0.f);
                float t2 = fmaxf(hadd2(acc[pp][2]) + bov[2], 0.f);
                float t3 = fmaxf(hadd2(acc[pp][3]) + bov[3], 0.f);
                r.x = o.x + t0; r.x = (r.x >= 0.f) ? r.x : pa * r.x;
                r.y = o.y + t1; r.y = (r.y >= 0.f) ? r.y : pa * r.y;
                r.z = o.z + t2; r.z = (r.z >= 0.f) ? r.z : pa * r.z;
                r.w = o.w + t3; r.w = (r.w >= 0.f) ? r.w : pa * r.w;
                *(float4*)&out[(size_t)p * CC + c0] = r;
            }
        }
    }
}

// ---------------- launch ----------------
extern "C" void kernel_launch(void* const* d_in, const int* in_sizes, int n_in,
                              void* d_out, int out_size) {
    int off = (n_in >= 13) ? 1 : 0;
    const float* x   = (const float*)d_in[0];
    const int*   poi = (const int*)d_in[1];
    const float* Wq  = (const float*)d_in[2 + off];
    const float* bq  = (const float*)d_in[3 + off];
    const float* Wk  = (const float*)d_in[4 + off];
    const float* bk  = (const float*)d_in[5 + off];
    const float* Wv  = (const float*)d_in[6 + off];
    const float* bv  = (const float*)d_in[7 + off];
    const float* Wo  = (const float*)d_in[8 + off];
    const float* bo  = (const float*)d_in[9 + off];
    const float* S   = (const float*)d_in[10 + off];
    const float* pa  = (const float*)d_in[11 + off];
    float* out = (float*)d_out;

    int N = in_sizes[0] / CC;
    int P = out_size / CC;

    k_init<<<256, 256>>>(P);
    k_q<<<1, 256>>>(S, Wq, bq);
    k_qw<<<HH, 256>>>(Wk, bk);
    k_scores<<<(N + 31) / 32, 256>>>(x, poi, N);           // 8 warps * 4 checkins
    k_scan<<<1, 1024>>>(P);
    k_exp_scatter<<<(N + 255) / 256, 256>>>(poi, N);
    k_gather<<<(P + 7) / 8, 256>>>(x, P);
    k_fused<<<(P + TP - 1) / TP, 256>>>(Wv, Wo, bv, bo, pa, out, P);
}

// round 4
// speedup vs baseline: 1.3011x; 1.3011x over previous
#include <cuda_runtime.h>
#include <math.h>

#define CC 256
#define HH 4
#define NMAX 500000
#define PMAX 50000
#define TP 32

typedef unsigned long long ull;

// ---------------- device scratch ----------------
__device__ float    g_Q[CC];
__device__ float    g_qw[HH * CC];
__device__ float    g_qc[HH];
__device__ float    g_scoreE[(size_t)NMAX * HH];
__device__ unsigned g_smax[PMAX * HH];
__device__ float    g_denom[PMAX * HH];
__device__ int      g_count[PMAX];
__device__ int      g_offsets[PMAX + 1];
__device__ int      g_fill[PMAX];
__device__ int      g_order[NMAX];
__device__ float    g_xbar[(size_t)PMAX * HH * CC];

// ---------------- helpers ----------------
__device__ __forceinline__ unsigned encf(float f) {
    unsigned u = __float_as_uint(f);
    return (u & 0x80000000u) ? ~u : (u | 0x80000000u);
}
__device__ __forceinline__ float decf(unsigned u) {
    return (u & 0x80000000u) ? __uint_as_float(u ^ 0x80000000u) : __uint_as_float(~u);
}
__device__ __forceinline__ float hadd2(ull v) {
    float x, y;
    asm("mov.b64 {%0,%1}, %2;" : "=f"(x), "=f"(y) : "l"(v));
    return x + y;
}
__device__ __forceinline__ void fma2(ull& d, ull a, ull b) {
    asm("fma.rn.f32x2 %0, %1, %2, %0;" : "+l"(d) : "l"(a), "l"(b));
}

// ---------------- kernels ----------------
__global__ void k_init(int P) {
    int i = blockIdx.x * blockDim.x + threadIdx.x;
    int st = gridDim.x * blockDim.x;
    for (int j = i; j < P * HH; j += st) { g_smax[j] = 0u; g_denom[j] = 0.f; }
    for (int j = i; j < P; j += st)      { g_count[j] = 0;  g_fill[j] = 0; }
}

__global__ void k_q(const float* __restrict__ S, const float* __restrict__ Wq,
                    const float* __restrict__ bq) {
    __shared__ float sS[CC];
    int c = threadIdx.x;
    sS[c] = S[c];
    __syncthreads();
    const float4* wr = (const float4*)(Wq + (size_t)c * CC);
    float acc = 0.f;
    #pragma unroll 8
    for (int j = 0; j < CC / 4; j++) {
        float4 w = wr[j];
        acc += sS[4*j] * w.x + sS[4*j+1] * w.y + sS[4*j+2] * w.z + sS[4*j+3] * w.w;
    }
    g_Q[c] = acc + bq[c];
}

__global__ void k_qw(const float* __restrict__ Wk, const float* __restrict__ bk) {
    int h = blockIdx.x;
    int j = threadIdx.x;
    __shared__ float sQ[64];
    if (j < 64) sQ[j] = g_Q[h * 64 + j];
    __syncthreads();
    float acc = 0.f;
    #pragma unroll 8
    for (int cc = 0; cc < 64; cc++)
        acc += sQ[cc] * Wk[(size_t)(h * 64 + cc) * CC + j];
    g_qw[h * CC + j] = acc * 0.0625f;
    if (j == 0) {
        float q = 0.f;
        for (int cc = 0; cc < 64; cc++) q += sQ[cc] * bk[h * 64 + cc];
        g_qc[h] = q * 0.0625f;
    }
}

// warp handles 2 checkins; all 4 row-loads issued up front (MLP=4)
__global__ void k_scores(const float* __restrict__ x, const int* __restrict__ poi, int N) {
    int lane = threadIdx.x & 31;
    int gw = (blockIdx.x * blockDim.x + threadIdx.x) >> 5;
    int n0 = gw * 2;
    if (n0 >= N) return;
    bool has2 = (n0 + 1 < N);
    int n1 = has2 ? n0 + 1 : n0;

    const float4* xa = (const float4*)(x + (size_t)n0 * CC);
    const float4* xb = (const float4*)(x + (size_t)n1 * CC);
    float4 a0 = xa[lane];
    float4 a1 = xa[32 + lane];
    float4 b0 = xb[lane];
    float4 b1 = xb[32 + lane];

    float4 q0[HH], q1[HH];
    #pragma unroll
    for (int h = 0; h < HH; h++) {
        q0[h] = *(const float4*)&g_qw[h * CC + lane * 4];
        q1[h] = *(const float4*)&g_qw[h * CC + 128 + lane * 4];
    }
    float accA[HH], accB[HH];
    #pragma unroll
    for (int h = 0; h < HH; h++) {
        accA[h] = a0.x * q0[h].x + a0.y * q0[h].y + a0.z * q0[h].z + a0.w * q0[h].w
                + a1.x * q1[h].x + a1.y * q1[h].y + a1.z * q1[h].z + a1.w * q1[h].w;
        accB[h] = b0.x * q0[h].x + b0.y * q0[h].y + b0.z * q0[h].z + b0.w * q0[h].w
                + b1.x * q1[h].x + b1.y * q1[h].y + b1.z * q1[h].z + b1.w * q1[h].w;
    }
    #pragma unroll
    for (int off = 16; off > 0; off >>= 1) {
        #pragma unroll
        for (int h = 0; h < HH; h++) {
            accA[h] += __shfl_xor_sync(0xffffffffu, accA[h], off);
            accB[h] += __shfl_xor_sync(0xffffffffu, accB[h], off);
        }
    }
    if (lane == 0) {
        float qc0 = g_qc[0], qc1 = g_qc[1], qc2 = g_qc[2], qc3 = g_qc[3];
        {
            int p = poi[n0];
            float s0 = accA[0] + qc0, s1 = accA[1] + qc1;
            float s2 = accA[2] + qc2, s3 = accA[3] + qc3;
            atomicMax(&g_smax[p * 4 + 0], encf(s0));
            atomicMax(&g_smax[p * 4 + 1], encf(s1));
            atomicMax(&g_smax[p * 4 + 2], encf(s2));
            atomicMax(&g_smax[p * 4 + 3], encf(s3));
            *(float4*)&g_scoreE[(size_t)n0 * 4] = make_float4(s0, s1, s2, s3);
            atomicAdd(&g_count[p], 1);
        }
        if (has2) {
            int p = poi[n1];
            float s0 = accB[0] + qc0, s1 = accB[1] + qc1;
            float s2 = accB[2] + qc2, s3 = accB[3] + qc3;
            atomicMax(&g_smax[p * 4 + 0], encf(s0));
            atomicMax(&g_smax[p * 4 + 1], encf(s1));
            atomicMax(&g_smax[p * 4 + 2], encf(s2));
            atomicMax(&g_smax[p * 4 + 3], encf(s3));
            *(float4*)&g_scoreE[(size_t)n1 * 4] = make_float4(s0, s1, s2, s3);
            atomicAdd(&g_count[p], 1);
        }
    }
}

__global__ void k_scan(int P) {
    __shared__ int s[1024];
    int t = threadIdx.x;
    int chunk = (P + 1023) / 1024;
    int beg = t * chunk, end = min(beg + chunk, P);
    int sum = 0;
    for (int i = beg; i < end; i++) sum += g_count[i];
    s[t] = sum;
    __syncthreads();
    for (int off = 1; off < 1024; off <<= 1) {
        int v = (t >= off) ? s[t - off] : 0;
        __syncthreads();
        s[t] += v;
        __syncthreads();
    }
    int run = s[t] - sum;
    for (int i = beg; i < end; i++) { g_offsets[i] = run; run += g_count[i]; }
    if (t == 1023) g_offsets[P] = s[1023];
}

__global__ void k_exp_scatter(const int* __restrict__ poi, int N) {
    int n = blockIdx.x * blockDim.x + threadIdx.x;
    if (n >= N) return;
    float4 s = *(const float4*)&g_scoreE[(size_t)n * 4];
    int p = poi[n];
    float e0 = expf(s.x - decf(g_smax[p * 4 + 0]));
    float e1 = expf(s.y - decf(g_smax[p * 4 + 1]));
    float e2 = expf(s.z - decf(g_smax[p * 4 + 2]));
    float e3 = expf(s.w - decf(g_smax[p * 4 + 3]));
    *(float4*)&g_scoreE[(size_t)n * 4] = make_float4(e0, e1, e2, e3);
    atomicAdd(&g_denom[p * 4 + 0], e0);
    atomicAdd(&g_denom[p * 4 + 1], e1);
    atomicAdd(&g_denom[p * 4 + 2], e2);
    atomicAdd(&g_denom[p * 4 + 3], e3);
    int pos = g_offsets[p] + atomicAdd(&g_fill[p], 1);
    g_order[pos] = n;
}

__global__ void k_gather(const float* __restrict__ x, int P) {
    int lane = threadIdx.x & 31;
    int p = (blockIdx.x * blockDim.x + threadIdx.x) >> 5;
    if (p >= P) return;
    int beg = g_offsets[p], end = g_offsets[p + 1];
    float rinv[HH];
    #pragma unroll
    for (int h = 0; h < HH; h++) rinv[h] = 1.0f / (g_denom[p * 4 + h] + 1e-16f);
    float a0[HH][4], a1[HH][4];
    #pragma unroll
    for (int h = 0; h < HH; h++)
        #pragma unroll
        for (int k = 0; k < 4; k++) { a0[h][k] = 0.f; a1[h][k] = 0.f; }
    int n = (beg < end) ? g_order[beg] : 0;
    for (int i = beg; i < end; i++) {
        int nn = (i + 1 < end) ? g_order[i + 1] : 0;
        float4 e = *(const float4*)&g_scoreE[(size_t)n * 4];
        const float4* xr = (const float4*)(x + (size_t)n * CC);
        float4 v0 = xr[lane];
        float4 v1 = xr[32 + lane];
        float al[HH] = { e.x * rinv[0], e.y * rinv[1], e.z * rinv[2], e.w * rinv[3] };
        #pragma unroll
        for (int h = 0; h < HH; h++) {
            a0[h][0] += al[h] * v0.x; a0[h][1] += al[h] * v0.y;
            a0[h][2] += al[h] * v0.z; a0[h][3] += al[h] * v0.w;
            a1[h][0] += al[h] * v1.x; a1[h][1] += al[h] * v1.y;
            a1[h][2] += al[h] * v1.z; a1[h][3] += al[h] * v1.w;
        }
        n = nn;
    }
    #pragma unroll
    for (int h = 0; h < HH; h++) {
        float* dst = &g_xbar[((size_t)p * HH + h) * CC];
        *(float4*)&dst[lane * 4]       = make_float4(a0[h][0], a0[h][1], a0[h][2], a0[h][3]);
        *(float4*)&dst[128 + lane * 4] = make_float4(a1[h][0], a1[h][1], a1[h][2], a1[h][3]);
    }
}

// Fused GEMMs, 2 cols x 16 rows per thread.
// Warp-uniform operand mapping: head = warp&3, rowgroup = warp>>2, so every
// smem x-operand read is a 32-lane broadcast (no crossbar conflicts).
__global__ void __launch_bounds__(256) k_fused(
    const float* __restrict__ Wv, const float* __restrict__ Wo,
    const float* __restrict__ bv, const float* __restrict__ bo,
    const float* __restrict__ prelu, float* __restrict__ out, int P)
{
    __shared__ float sO[TP * CC];          // 32 KB
    __shared__ float sX[TP * HH * 8];      // 4 KB
    int t = threadIdx.x;
    int w = t >> 5, lane = t & 31;
    int head = w & 3;
    int rbase = (w >> 2) * 16;             // 0 or 16
    int c0 = head * 64 + lane * 2;
    int p0 = blockIdx.x * TP;

    ull acc[16][2];
    #pragma unroll
    for (int pp = 0; pp < 16; pp++) { acc[pp][0] = 0ull; acc[pp][1] = 0ull; }

    const float* wv0 = Wv + (size_t)c0 * CC;
    const float* wv1 = Wv + (size_t)(c0 + 1) * CC;

    // ---- Phase A: O = Q + xbar @ Wv^T + bv*m ----
    for (int kc = 0; kc < CC / 8; kc++) {
        {
            int row = t >> 3, rem = t & 7, hh = rem >> 1, half = rem & 1;
            int p = p0 + row; if (p >= P) p = P - 1;
            *(float4*)&sX[(row * HH + hh) * 8 + half * 4] =
                *(const float4*)&g_xbar[((size_t)p * HH + hh) * CC + kc * 8 + half * 4];
        }
        __syncthreads();
        ull w0[4], w1[4];
        {
            longlong2 a = *(const longlong2*)(wv0 + kc * 8);
            longlong2 b = *(const longlong2*)(wv0 + kc * 8 + 4);
            w0[0] = (ull)a.x; w0[1] = (ull)a.y; w0[2] = (ull)b.x; w0[3] = (ull)b.y;
            longlong2 c = *(const longlong2*)(wv1 + kc * 8);
            longlong2 d = *(const longlong2*)(wv1 + kc * 8 + 4);
            w1[0] = (ull)c.x; w1[1] = (ull)c.y; w1[2] = (ull)d.x; w1[3] = (ull)d.y;
        }
        #pragma unroll
        for (int pp = 0; pp < 16; pp++) {
            const longlong2* sp = (const longlong2*)&sX[((rbase + pp) * HH + head) * 8];
            longlong2 a = sp[0], b = sp[1];
            fma2(acc[pp][0], (ull)a.x, w0[0]); fma2(acc[pp][1], (ull)a.x, w1[0]);
            fma2(acc[pp][0], (ull)a.y, w0[1]); fma2(acc[pp][1], (ull)a.y, w1[1]);
            fma2(acc[pp][0], (ull)b.x, w0[2]); fma2(acc[pp][1], (ull)b.x, w1[2]);
            fma2(acc[pp][0], (ull)b.y, w0[3]); fma2(acc[pp][1], (ull)b.y, w1[3]);
        }
        __syncthreads();
    }
    {
        float q0v = g_Q[c0], q1v = g_Q[c0 + 1];
        float b0v = bv[c0], b1v = bv[c0 + 1];
        #pragma unroll
        for (int pp = 0; pp < 16; pp++) {
            int p = p0 + rbase + pp; if (p >= P) p = P - 1;
            float d = g_denom[p * 4 + head];
            float m = d / (d + 1e-16f);
            float2 o = make_float2(hadd2(acc[pp][0]) + q0v + b0v * m,
                                   hadd2(acc[pp][1]) + q1v + b1v * m);
            *(float2*)&sO[(rbase + pp) * CC + c0] = o;
            acc[pp][0] = 0ull; acc[pp][1] = 0ull;
        }
    }
    __syncthreads();

    // ---- Phase B: out = prelu(O + relu(O @ Wo^T + bo)) ----
    const float* wo0 = Wo + (size_t)c0 * CC;
    const float* wo1 = Wo + (size_t)(c0 + 1) * CC;
    for (int kc = 0; kc < CC / 8; kc++) {
        ull w0[4], w1[4];
        {
            longlong2 a = *(const longlong2*)(wo0 + kc * 8);
            longlong2 b = *(const longlong2*)(wo0 + kc * 8 + 4);
            w0[0] = (ull)a.x; w0[1] = (ull)a.y; w0[2] = (ull)b.x; w0[3] = (ull)b.y;
            longlong2 c = *(const longlong2*)(wo1 + kc * 8);
            longlong2 d = *(const longlong2*)(wo1 + kc * 8 + 4);
            w1[0] = (ull)c.x; w1[1] = (ull)c.y; w1[2] = (ull)d.x; w1[3] = (ull)d.y;
        }
        #pragma unroll
        for (int pp = 0; pp < 16; pp++) {
            const longlong2* sp = (const longlong2*)&sO[(rbase + pp) * CC + kc * 8];
            longlong2 a = sp[0], b = sp[1];
            fma2(acc[pp][0], (ull)a.x, w0[0]); fma2(acc[pp][1], (ull)a.x, w1[0]);
            fma2(acc[pp][0], (ull)a.y, w0[1]); fma2(acc[pp][1], (ull)a.y, w1[1]);
            fma2(acc[pp][0], (ull)b.x, w0[2]); fma2(acc[pp][1], (ull)b.x, w1[2]);
            fma2(acc[pp][0], (ull)b.y, w0[3]); fma2(acc[pp][1], (ull)b.y, w1[3]);
        }
    }
    {
        float bo0 = bo[c0], bo1 = bo[c0 + 1];
        float pa = prelu[0];
        #pragma unroll
        for (int pp = 0; pp < 16; pp++) {
            int p = p0 + rbase + pp;
            if (p < P) {
                float2 o = *(const float2*)&sO[(rbase + pp) * CC + c0];
                float t0 = fmaxf(hadd2(acc[pp][0]) + bo0, 0.f);
                float t1 = fmaxf(hadd2(acc[pp][1]) + bo1, 0.f);
                float r0 = o.x + t0; r0 = (r0 >= 0.f) ? r0 : pa * r0;
                float r1 = o.y + t1; r1 = (r1 >= 0.f) ? r1 : pa * r1;
                *(float2*)&out[(size_t)p * CC + c0] = make_float2(r0, r1);
            }
        }
    }
}

// ---------------- launch ----------------
extern "C" void kernel_launch(void* const* d_in, const int* in_sizes, int n_in,
                              void* d_out, int out_size) {
    int off = (n_in >= 13) ? 1 : 0;
    const float* x   = (const float*)d_in[0];
    const int*   poi = (const int*)d_in[1];
    const float* Wq  = (const float*)d_in[2 + off];
    const float* bq  = (const float*)d_in[3 + off];
    const float* Wk  = (const float*)d_in[4 + off];
    const float* bk  = (const float*)d_in[5 + off];
    const float* Wv  = (const float*)d_in[6 + off];
    const float* bv  = (const float*)d_in[7 + off];
    const float* Wo  = (const float*)d_in[8 + off];
    const float* bo  = (const float*)d_in[9 + off];
    const float* S   = (const float*)d_in[10 + off];
    const float* pa  = (const float*)d_in[11 + off];
    float* out = (float*)d_out;

    int N = in_sizes[0] / CC;
    int P = out_size / CC;

    k_init<<<256, 256>>>(P);
    k_q<<<1, 256>>>(S, Wq, bq);
    k_qw<<<HH, 256>>>(Wk, bk);
    k_scores<<<(N + 15) / 16, 256>>>(x, poi, N);     // 8 warps * 2 checkins / block
    k_scan<<<1, 1024>>>(P);
    k_exp_scatter<<<(N + 255) / 256, 256>>>(poi, N);
    k_gather<<<(P + 7) / 8, 256>>>(x, P);
    k_fused<<<(P + TP - 1) / TP, 256>>>(Wv, Wo, bv, bo, pa, out, P);
}